// round 9
// baseline (speedup 1.0000x reference)
#include <cuda_runtime.h>
#include <math.h>

#define NB 32
#define NC 256
#define NH 64
#define NW 64
#define NHW 4096   // NH*NW

// Scratch (allocation-free: __device__ globals)
__device__ float g_pooled[NB * 2 * NHW];   // [b][{max,avg}][h*w] : 1 MiB
__device__ float g_att[NB * NHW];          // [b][h*w]            : 512 KiB

// ---------------------------------------------------------------------------
// Kernel 1: channel max + mean pooling.  One thread per (b, pixel).
// Warp = 32 consecutive pixels -> each channel iteration is a coalesced 128B line.
// Four independent accumulator pairs keep the reduction latency-hidden.
// ---------------------------------------------------------------------------
__global__ void __launch_bounds__(256) pool_kernel(const float* __restrict__ x) {
    unsigned t = blockIdx.x * 256u + threadIdx.x;   // 0 .. 131071
    unsigned b = t >> 12;
    unsigned p = t & 4095u;
    const float* xp = x + (size_t)b * NC * NHW + p;
    float mx0 = -INFINITY, mx1 = -INFINITY, mx2 = -INFINITY, mx3 = -INFINITY;
    float sm0 = 0.0f, sm1 = 0.0f, sm2 = 0.0f, sm3 = 0.0f;
#pragma unroll 2
    for (int c = 0; c < NC; c += 4) {
        float v0 = __ldg(xp + (size_t)(c + 0) * NHW);
        float v1 = __ldg(xp + (size_t)(c + 1) * NHW);
        float v2 = __ldg(xp + (size_t)(c + 2) * NHW);
        float v3 = __ldg(xp + (size_t)(c + 3) * NHW);
        mx0 = fmaxf(mx0, v0);  sm0 += v0;
        mx1 = fmaxf(mx1, v1);  sm1 += v1;
        mx2 = fmaxf(mx2, v2);  sm2 += v2;
        mx3 = fmaxf(mx3, v3);  sm3 += v3;
    }
    g_pooled[b * 2u * NHW + p]       = fmaxf(fmaxf(mx0, mx1), fmaxf(mx2, mx3));
    g_pooled[b * 2u * NHW + NHW + p] = ((sm0 + sm1) + (sm2 + sm3)) * (1.0f / NC);
}

// ---------------------------------------------------------------------------
// Kernel 2: three 7x7 conv(2->1) + BN + sigmoid branches, averaged -> g_att.
// One block = 4-row strip of one image (256 threads, one per pixel).
// Pooled halo tile + weights live in SMEM. Branch 2's HW transpose is folded
// into a spatial transpose of its weights (valid: H=W, symmetric padding).
// ---------------------------------------------------------------------------
__global__ void __launch_bounds__(256) att_kernel(
    const float* __restrict__ w1, const float* __restrict__ g1, const float* __restrict__ b1,
    const float* __restrict__ m1, const float* __restrict__ v1,
    const float* __restrict__ w2, const float* __restrict__ g2, const float* __restrict__ b2,
    const float* __restrict__ m2, const float* __restrict__ v2,
    const float* __restrict__ w3, const float* __restrict__ g3, const float* __restrict__ b3,
    const float* __restrict__ m3, const float* __restrict__ v3)
{
    __shared__ float tile[2][10][70];   // 2 ch x (4+6) rows x (64+6) cols
    __shared__ float sw[3][2][49];      // [branch][ch][7*7]
    __shared__ float sc[3], sh[3];      // BN scale / shift

    unsigned b  = blockIdx.x >> 4;           // image
    unsigned h0 = (blockIdx.x & 15u) * 4u;   // first output row of this strip

    // Load all 3 weight sets (294 floats). Branch index 1 (w2) stored transposed.
    for (int j = threadIdx.x; j < 294; j += 256) {
        int br  = j / 98;
        int rem = j - br * 98;
        int c   = rem / 49;
        int k   = rem - c * 49;
        const float* src = (br == 0) ? w1 : (br == 1) ? w2 : w3;
        float v = __ldg(src + c * 49 + k);
        int kd = k;
        if (br == 1) { int ky = k / 7, kx = k - ky * 7; kd = kx * 7 + ky; }
        sw[br][c][kd] = v;
    }
    if (threadIdx.x == 0) {
        sc[0] = __ldg(g1) * rsqrtf(__ldg(v1) + 1e-5f);  sh[0] = __ldg(b1) - __ldg(m1) * sc[0];
        sc[1] = __ldg(g2) * rsqrtf(__ldg(v2) + 1e-5f);  sh[1] = __ldg(b2) - __ldg(m2) * sc[1];
        sc[2] = __ldg(g3) * rsqrtf(__ldg(v3) + 1e-5f);  sh[2] = __ldg(b3) - __ldg(m3) * sc[2];
    }

    // Load pooled halo tile (zero-padded), 1400 elements.
    const float* pb = g_pooled + (size_t)b * (2 * NHW);
    for (int j = threadIdx.x; j < 1400; j += 256) {
        int ch = j / 700;
        int r  = (j - ch * 700) / 70;
        int cc = j - ch * 700 - r * 70;
        int gh = (int)h0 - 3 + r;
        int gw = cc - 3;
        float v = 0.0f;
        if (gh >= 0 && gh < NH && gw >= 0 && gw < NW)
            v = pb[ch * NHW + gh * NW + gw];
        tile[ch][r][cc] = v;
    }
    __syncthreads();

    int tr = threadIdx.x >> 6;   // 0..3
    int tc = threadIdx.x & 63;   // 0..63
    float a0 = 0.0f, a1 = 0.0f, a2 = 0.0f;
#pragma unroll
    for (int ky = 0; ky < 7; ++ky) {
#pragma unroll
        for (int kx = 0; kx < 7; ++kx) {
            float pm = tile[0][tr + ky][tc + kx];
            float pa = tile[1][tr + ky][tc + kx];
            int k = ky * 7 + kx;
            a0 = fmaf(pm, sw[0][0][k], a0);
            a0 = fmaf(pa, sw[0][1][k], a0);
            a1 = fmaf(pm, sw[1][0][k], a1);
            a1 = fmaf(pa, sw[1][1][k], a1);
            a2 = fmaf(pm, sw[2][0][k], a2);
            a2 = fmaf(pa, sw[2][1][k], a2);
        }
    }
    float s0 = 1.0f / (1.0f + expf(-(a0 * sc[0] + sh[0])));
    float s1 = 1.0f / (1.0f + expf(-(a1 * sc[1] + sh[1])));
    float s2 = 1.0f / (1.0f + expf(-(a2 * sc[2] + sh[2])));

    unsigned p = (h0 + (unsigned)tr) * NW + (unsigned)tc;
    g_att[b * NHW + p] = (s0 + s1 + s2) * (1.0f / 3.0f);
}

// ---------------------------------------------------------------------------
// Kernel 3: out = x * att  (float4 streaming; att is L2-resident, reused 256x)
// Each thread handles 2 float4s to cut grid size / tail overhead.
// ---------------------------------------------------------------------------
__global__ void __launch_bounds__(256) mul_kernel(const float* __restrict__ x,
                                                  float* __restrict__ out) {
    unsigned base = (blockIdx.x * 256u + threadIdx.x) * 2u;  // float4 index
#pragma unroll
    for (int i = 0; i < 2; ++i) {
        unsigned t = base + (unsigned)i;
        unsigned e = t << 2;              // element index
        unsigned b = e >> 20;             // / (C*H*W)
        unsigned p = e & 4095u;           // pixel within plane
        float4 xv = __ldg((const float4*)x + t);
        float4 av = *(const float4*)(g_att + (b << 12) + p);
        float4 o;
        o.x = xv.x * av.x;
        o.y = xv.y * av.y;
        o.z = xv.z * av.z;
        o.w = xv.w * av.w;
        ((float4*)out)[t] = o;
    }
}

// ---------------------------------------------------------------------------
extern "C" void kernel_launch(void* const* d_in, const int* in_sizes, int n_in,
                              void* d_out, int out_size) {
    const float* x  = (const float*)d_in[0];
    const float* w1 = (const float*)d_in[1];
    const float* g1 = (const float*)d_in[2];
    const float* b1 = (const float*)d_in[3];
    const float* m1 = (const float*)d_in[4];
    const float* v1 = (const float*)d_in[5];
    const float* w2 = (const float*)d_in[6];
    const float* g2 = (const float*)d_in[7];
    const float* b2 = (const float*)d_in[8];
    const float* m2 = (const float*)d_in[9];
    const float* v2 = (const float*)d_in[10];
    const float* w3 = (const float*)d_in[11];
    const float* g3 = (const float*)d_in[12];
    const float* b3 = (const float*)d_in[13];
    const float* m3 = (const float*)d_in[14];
    const float* v3 = (const float*)d_in[15];
    float* out = (float*)d_out;

    pool_kernel<<<(NB * NHW) / 256, 256>>>(x);
    att_kernel<<<NB * (NH / 4), 256>>>(w1, g1, b1, m1, v1,
                                       w2, g2, b2, m2, v2,
                                       w3, g3, b3, m3, v3);
    // 32*256*4096 float elems / 4 per float4 / (256 threads * 2 per thread) = 16384 blocks
    mul_kernel<<<(NB * NC * NHW / 4) / (256 * 2), 256>>>(x, out);
}

// round 10
// speedup vs baseline: 1.1035x; 1.1035x over previous
#include <cuda_runtime.h>
#include <math.h>

#define NB 32
#define NC 256
#define NH 64
#define NW 64
#define NHW 4096   // NH*NW
#define PSPLIT 4   // channel splits in pool phase (64 channels each)

// Scratch (allocation-free: __device__ globals)
__device__ float g_pmax[NB * PSPLIT * NHW];  // partial channel max  : 2 MiB
__device__ float g_psum[NB * PSPLIT * NHW];  // partial channel sum  : 2 MiB
__device__ float g_att[NB * NHW];            // attention map        : 512 KiB

// ---------------------------------------------------------------------------
// Kernel 1: partial channel max/sum.  Channel dim split 4x for occupancy:
// 524288 threads = 2048 blocks (~14 blocks/SM -> full occupancy, vs 41% before).
// Each thread reduces 64 channels for one (b, pixel, split).
// ---------------------------------------------------------------------------
__global__ void __launch_bounds__(256) pool_kernel(const float* __restrict__ x) {
    unsigned t = blockIdx.x * 256u + threadIdx.x;   // 0 .. 524287
    unsigned b = t >> 14;            // / (PSPLIT*NHW)
    unsigned s = (t >> 12) & 3u;     // channel split
    unsigned p = t & 4095u;          // pixel
    const float* xp = x + (size_t)b * NC * NHW + (size_t)(s * 64u) * NHW + p;
    float mx0 = -INFINITY, mx1 = -INFINITY, mx2 = -INFINITY, mx3 = -INFINITY;
    float sm0 = 0.0f, sm1 = 0.0f, sm2 = 0.0f, sm3 = 0.0f;
#pragma unroll 4
    for (int c = 0; c < 64; c += 4) {
        float v0 = __ldg(xp + (size_t)(c + 0) * NHW);
        float v1 = __ldg(xp + (size_t)(c + 1) * NHW);
        float v2 = __ldg(xp + (size_t)(c + 2) * NHW);
        float v3 = __ldg(xp + (size_t)(c + 3) * NHW);
        mx0 = fmaxf(mx0, v0);  sm0 += v0;
        mx1 = fmaxf(mx1, v1);  sm1 += v1;
        mx2 = fmaxf(mx2, v2);  sm2 += v2;
        mx3 = fmaxf(mx3, v3);  sm3 += v3;
    }
    g_pmax[t] = fmaxf(fmaxf(mx0, mx1), fmaxf(mx2, mx3));
    g_psum[t] = ((sm0 + sm1) + (sm2 + sm3));
}

// ---------------------------------------------------------------------------
// Kernel 2: combine partials + three 7x7 conv(2->1) + BN + sigmoid, averaged.
// One block = 4-row strip of one image (256 threads, one per pixel).
// Halo tile loads combine the 4 pool partials inline (all L2-resident).
// Branch 2's HW transpose is folded into a spatial transpose of its weights
// (valid: H=W, symmetric padding).
// ---------------------------------------------------------------------------
__global__ void __launch_bounds__(256) att_kernel(
    const float* __restrict__ w1, const float* __restrict__ g1, const float* __restrict__ b1,
    const float* __restrict__ m1, const float* __restrict__ v1,
    const float* __restrict__ w2, const float* __restrict__ g2, const float* __restrict__ b2,
    const float* __restrict__ m2, const float* __restrict__ v2,
    const float* __restrict__ w3, const float* __restrict__ g3, const float* __restrict__ b3,
    const float* __restrict__ m3, const float* __restrict__ v3)
{
    __shared__ float tile[2][10][70];   // 2 ch x (4+6) rows x (64+6) cols
    __shared__ float sw[3][2][49];      // [branch][ch][7*7]
    __shared__ float sc[3], sh[3];      // BN scale / shift

    unsigned b  = blockIdx.x >> 4;           // image
    unsigned h0 = (blockIdx.x & 15u) * 4u;   // first output row of this strip

    // Load all 3 weight sets (294 floats). Branch index 1 (w2) stored transposed.
    for (int j = threadIdx.x; j < 294; j += 256) {
        int br  = j / 98;
        int rem = j - br * 98;
        int c   = rem / 49;
        int k   = rem - c * 49;
        const float* src = (br == 0) ? w1 : (br == 1) ? w2 : w3;
        float v = __ldg(src + c * 49 + k);
        int kd = k;
        if (br == 1) { int ky = k / 7, kx = k - ky * 7; kd = kx * 7 + ky; }
        sw[br][c][kd] = v;
    }
    if (threadIdx.x == 0) {
        sc[0] = __ldg(g1) * rsqrtf(__ldg(v1) + 1e-5f);  sh[0] = __ldg(b1) - __ldg(m1) * sc[0];
        sc[1] = __ldg(g2) * rsqrtf(__ldg(v2) + 1e-5f);  sh[1] = __ldg(b2) - __ldg(m2) * sc[1];
        sc[2] = __ldg(g3) * rsqrtf(__ldg(v3) + 1e-5f);  sh[2] = __ldg(b3) - __ldg(m3) * sc[2];
    }

    // Load pooled halo tile (zero-padded), 1400 elements; combine 4 partials.
    unsigned pbase = b * (PSPLIT * NHW);
    for (int j = threadIdx.x; j < 1400; j += 256) {
        int ch = j / 700;
        int r  = (j - ch * 700) / 70;
        int cc = j - ch * 700 - r * 70;
        int gh = (int)h0 - 3 + r;
        int gw = cc - 3;
        float v = 0.0f;
        if (gh >= 0 && gh < NH && gw >= 0 && gw < NW) {
            unsigned pix = (unsigned)(gh * NW + gw);
            if (ch == 0) {
                float a = g_pmax[pbase + 0 * NHW + pix];
                float bb = g_pmax[pbase + 1 * NHW + pix];
                float c2 = g_pmax[pbase + 2 * NHW + pix];
                float d = g_pmax[pbase + 3 * NHW + pix];
                v = fmaxf(fmaxf(a, bb), fmaxf(c2, d));
            } else {
                float a = g_psum[pbase + 0 * NHW + pix];
                float bb = g_psum[pbase + 1 * NHW + pix];
                float c2 = g_psum[pbase + 2 * NHW + pix];
                float d = g_psum[pbase + 3 * NHW + pix];
                v = ((a + bb) + (c2 + d)) * (1.0f / NC);
            }
        }
        tile[ch][r][cc] = v;
    }
    __syncthreads();

    int tr = threadIdx.x >> 6;   // 0..3
    int tc = threadIdx.x & 63;   // 0..63
    float a0 = 0.0f, a1 = 0.0f, a2 = 0.0f;
#pragma unroll
    for (int ky = 0; ky < 7; ++ky) {
#pragma unroll
        for (int kx = 0; kx < 7; ++kx) {
            float pm = tile[0][tr + ky][tc + kx];
            float pa = tile[1][tr + ky][tc + kx];
            int k = ky * 7 + kx;
            a0 = fmaf(pm, sw[0][0][k], a0);
            a0 = fmaf(pa, sw[0][1][k], a0);
            a1 = fmaf(pm, sw[1][0][k], a1);
            a1 = fmaf(pa, sw[1][1][k], a1);
            a2 = fmaf(pm, sw[2][0][k], a2);
            a2 = fmaf(pa, sw[2][1][k], a2);
        }
    }
    float s0 = 1.0f / (1.0f + expf(-(a0 * sc[0] + sh[0])));
    float s1 = 1.0f / (1.0f + expf(-(a1 * sc[1] + sh[1])));
    float s2 = 1.0f / (1.0f + expf(-(a2 * sc[2] + sh[2])));

    unsigned p = (h0 + (unsigned)tr) * NW + (unsigned)tc;
    g_att[b * NHW + p] = (s0 + s1 + s2) * (1.0f / 3.0f);
}

// ---------------------------------------------------------------------------
// Kernel 3: out = x * att.  Channel-loop form: each thread owns one float4
// pixel-group and 16 channels, loading att ONCE into registers (256x less att
// traffic than the pixel-loop form).  524288 threads = 2048 blocks.
// ---------------------------------------------------------------------------
__global__ void __launch_bounds__(256) mul_kernel(const float* __restrict__ x,
                                                  float* __restrict__ out) {
    unsigned t = blockIdx.x * 256u + threadIdx.x;  // 0 .. 524287
    unsigned b = t >> 14;            // / (16 * 1024)
    unsigned s = (t >> 10) & 15u;    // channel group (16 channels)
    unsigned q = t & 1023u;          // float4 index within plane (1024 per plane)

    float4 av = *(const float4*)(g_att + (b << 12) + (q << 2));

    const float4* xq = (const float4*)x + ((size_t)(b * 256u + s * 16u) << 10) + q;
    float4* oq = (float4*)out + ((size_t)(b * 256u + s * 16u) << 10) + q;
#pragma unroll 4
    for (int c = 0; c < 16; ++c) {
        float4 xv = __ldg(xq + ((size_t)c << 10));
        float4 o;
        o.x = xv.x * av.x;
        o.y = xv.y * av.y;
        o.z = xv.z * av.z;
        o.w = xv.w * av.w;
        oq[(size_t)c << 10] = o;
    }
}

// ---------------------------------------------------------------------------
extern "C" void kernel_launch(void* const* d_in, const int* in_sizes, int n_in,
                              void* d_out, int out_size) {
    const float* x  = (const float*)d_in[0];
    const float* w1 = (const float*)d_in[1];
    const float* g1 = (const float*)d_in[2];
    const float* b1 = (const float*)d_in[3];
    const float* m1 = (const float*)d_in[4];
    const float* v1 = (const float*)d_in[5];
    const float* w2 = (const float*)d_in[6];
    const float* g2 = (const float*)d_in[7];
    const float* b2 = (const float*)d_in[8];
    const float* m2 = (const float*)d_in[9];
    const float* v2 = (const float*)d_in[10];
    const float* w3 = (const float*)d_in[11];
    const float* g3 = (const float*)d_in[12];
    const float* b3 = (const float*)d_in[13];
    const float* m3 = (const float*)d_in[14];
    const float* v3 = (const float*)d_in[15];
    float* out = (float*)d_out;

    pool_kernel<<<(NB * PSPLIT * NHW) / 256, 256>>>(x);          // 2048 blocks
    att_kernel<<<NB * (NH / 4), 256>>>(w1, g1, b1, m1, v1,
                                       w2, g2, b2, m2, v2,
                                       w3, g3, b3, m3, v3);      // 512 blocks
    mul_kernel<<<(NB * 16 * 1024) / 256, 256>>>(x, out);         // 2048 blocks
}

// round 16
// speedup vs baseline: 1.1267x; 1.0210x over previous
#include <cuda_runtime.h>
#include <math.h>

#define NB 32
#define NC 256
#define NH 64
#define NW 64
#define NHW 4096   // NH*NW
#define PSPLIT 8   // channel splits in pool phase (32 channels each)
#define NQ 1024    // float4 groups per plane (NHW/4)

// Scratch (allocation-free: __device__ globals)
__device__ float4 g_pmax4[NB * PSPLIT * NQ];  // partial channel max : 4 MiB
__device__ float4 g_psum4[NB * PSPLIT * NQ];  // partial channel sum : 4 MiB
__device__ float  g_att[NB * NHW];            // attention map       : 512 KiB

// ---------------------------------------------------------------------------
// Kernel 1: partial channel max/sum, float4 over pixels.
// 262144 threads = 1024 blocks. Each thread reduces 32 channels for one
// (b, split, float4-pixel-group): 32x 16B coalesced loads, 8 indep acc chains.
// ---------------------------------------------------------------------------
__global__ void __launch_bounds__(256) pool_kernel(const float* __restrict__ x) {
    unsigned t = blockIdx.x * 256u + threadIdx.x;   // 0 .. 262143
    unsigned b = t >> 13;            // / (PSPLIT*NQ)
    unsigned s = (t >> 10) & 7u;     // channel split
    unsigned q = t & 1023u;          // float4 group within plane

    const float4* xp = (const float4*)x + (size_t)b * NC * NQ + (size_t)(s * 32u) * NQ + q;

    float4 mxA = make_float4(-INFINITY, -INFINITY, -INFINITY, -INFINITY);
    float4 mxB = mxA;
    float4 smA = make_float4(0.f, 0.f, 0.f, 0.f);
    float4 smB = smA;
#pragma unroll 8
    for (int c = 0; c < 32; c += 2) {
        float4 vA = __ldg(xp + (size_t)(c + 0) * NQ);
        float4 vB = __ldg(xp + (size_t)(c + 1) * NQ);
        mxA.x = fmaxf(mxA.x, vA.x); smA.x += vA.x;
        mxA.y = fmaxf(mxA.y, vA.y); smA.y += vA.y;
        mxA.z = fmaxf(mxA.z, vA.z); smA.z += vA.z;
        mxA.w = fmaxf(mxA.w, vA.w); smA.w += vA.w;
        mxB.x = fmaxf(mxB.x, vB.x); smB.x += vB.x;
        mxB.y = fmaxf(mxB.y, vB.y); smB.y += vB.y;
        mxB.z = fmaxf(mxB.z, vB.z); smB.z += vB.z;
        mxB.w = fmaxf(mxB.w, vB.w); smB.w += vB.w;
    }
    float4 mx, sm;
    mx.x = fmaxf(mxA.x, mxB.x); sm.x = smA.x + smB.x;
    mx.y = fmaxf(mxA.y, mxB.y); sm.y = smA.y + smB.y;
    mx.z = fmaxf(mxA.z, mxB.z); sm.z = smA.z + smB.z;
    mx.w = fmaxf(mxA.w, mxB.w); sm.w = smA.w + smB.w;
    g_pmax4[t] = mx;
    g_psum4[t] = sm;
}

// ---------------------------------------------------------------------------
// Kernel 2: combine partials + three 7x7 conv(2->1) + BN + sigmoid, averaged.
// One block = 4-row strip of one image (256 threads, one per pixel).
// Halo tile loads combine the 8 pool partials inline (all L2-resident).
// Partial float layout: ((float*)g_pmax4)[b*32768 + s*4096 + pix].
// Branch 2's HW transpose is folded into a spatial transpose of its weights
// (valid: H=W, symmetric padding).
// ---------------------------------------------------------------------------
__global__ void __launch_bounds__(256) att_kernel(
    const float* __restrict__ w1, const float* __restrict__ g1, const float* __restrict__ b1,
    const float* __restrict__ m1, const float* __restrict__ v1,
    const float* __restrict__ w2, const float* __restrict__ g2, const float* __restrict__ b2,
    const float* __restrict__ m2, const float* __restrict__ v2,
    const float* __restrict__ w3, const float* __restrict__ g3, const float* __restrict__ b3,
    const float* __restrict__ m3, const float* __restrict__ v3)
{
    __shared__ float tile[2][10][70];   // 2 ch x (4+6) rows x (64+6) cols
    __shared__ float sw[3][2][49];      // [branch][ch][7*7]
    __shared__ float sc[3], sh[3];      // BN scale / shift

    unsigned b  = blockIdx.x >> 4;           // image
    unsigned h0 = (blockIdx.x & 15u) * 4u;   // first output row of this strip

    // Load all 3 weight sets (294 floats). Branch index 1 (w2) stored transposed.
    for (int j = threadIdx.x; j < 294; j += 256) {
        int br  = j / 98;
        int rem = j - br * 98;
        int c   = rem / 49;
        int k   = rem - c * 49;
        const float* src = (br == 0) ? w1 : (br == 1) ? w2 : w3;
        float v = __ldg(src + c * 49 + k);
        int kd = k;
        if (br == 1) { int ky = k / 7, kx = k - ky * 7; kd = kx * 7 + ky; }
        sw[br][c][kd] = v;
    }
    if (threadIdx.x == 0) {
        sc[0] = __ldg(g1) * rsqrtf(__ldg(v1) + 1e-5f);  sh[0] = __ldg(b1) - __ldg(m1) * sc[0];
        sc[1] = __ldg(g2) * rsqrtf(__ldg(v2) + 1e-5f);  sh[1] = __ldg(b2) - __ldg(m2) * sc[1];
        sc[2] = __ldg(g3) * rsqrtf(__ldg(v3) + 1e-5f);  sh[2] = __ldg(b3) - __ldg(m3) * sc[2];
    }

    // Load pooled halo tile (zero-padded), 1400 elements; combine 8 partials.
    const float* pmax = (const float*)g_pmax4 + (size_t)b * (PSPLIT * NHW);
    const float* psum = (const float*)g_psum4 + (size_t)b * (PSPLIT * NHW);
    for (int j = threadIdx.x; j < 1400; j += 256) {
        int ch = j / 700;
        int r  = (j - ch * 700) / 70;
        int cc = j - ch * 700 - r * 70;
        int gh = (int)h0 - 3 + r;
        int gw = cc - 3;
        float v = 0.0f;
        if (gh >= 0 && gh < NH && gw >= 0 && gw < NW) {
            unsigned pix = (unsigned)(gh * NW + gw);
            if (ch == 0) {
                float m01 = fmaxf(pmax[0 * NHW + pix], pmax[1 * NHW + pix]);
                float m23 = fmaxf(pmax[2 * NHW + pix], pmax[3 * NHW + pix]);
                float m45 = fmaxf(pmax[4 * NHW + pix], pmax[5 * NHW + pix]);
                float m67 = fmaxf(pmax[6 * NHW + pix], pmax[7 * NHW + pix]);
                v = fmaxf(fmaxf(m01, m23), fmaxf(m45, m67));
            } else {
                float s01 = psum[0 * NHW + pix] + psum[1 * NHW + pix];
                float s23 = psum[2 * NHW + pix] + psum[3 * NHW + pix];
                float s45 = psum[4 * NHW + pix] + psum[5 * NHW + pix];
                float s67 = psum[6 * NHW + pix] + psum[7 * NHW + pix];
                v = ((s01 + s23) + (s45 + s67)) * (1.0f / NC);
            }
        }
        tile[ch][r][cc] = v;
    }
    __syncthreads();

    int tr = threadIdx.x >> 6;   // 0..3
    int tc = threadIdx.x & 63;   // 0..63
    float a0 = 0.0f, a1 = 0.0f, a2 = 0.0f;
#pragma unroll
    for (int ky = 0; ky < 7; ++ky) {
#pragma unroll
        for (int kx = 0; kx < 7; ++kx) {
            float pm = tile[0][tr + ky][tc + kx];
            float pa = tile[1][tr + ky][tc + kx];
            int k = ky * 7 + kx;
            a0 = fmaf(pm, sw[0][0][k], a0);
            a0 = fmaf(pa, sw[0][1][k], a0);
            a1 = fmaf(pm, sw[1][0][k], a1);
            a1 = fmaf(pa, sw[1][1][k], a1);
            a2 = fmaf(pm, sw[2][0][k], a2);
            a2 = fmaf(pa, sw[2][1][k], a2);
        }
    }
    float s0 = 1.0f / (1.0f + expf(-(a0 * sc[0] + sh[0])));
    float s1 = 1.0f / (1.0f + expf(-(a1 * sc[1] + sh[1])));
    float s2 = 1.0f / (1.0f + expf(-(a2 * sc[2] + sh[2])));

    unsigned p = (h0 + (unsigned)tr) * NW + (unsigned)tc;
    g_att[b * NHW + p] = (s0 + s1 + s2) * (1.0f / 3.0f);
}

// ---------------------------------------------------------------------------
// Kernel 3: out = x * att.  Channel-loop form: each thread owns one float4
// pixel-group and 16 channels, loading att ONCE into registers (256x less att
// traffic than the pixel-loop form).  524288 threads = 2048 blocks.
// ---------------------------------------------------------------------------
__global__ void __launch_bounds__(256) mul_kernel(const float* __restrict__ x,
                                                  float* __restrict__ out) {
    unsigned t = blockIdx.x * 256u + threadIdx.x;  // 0 .. 524287
    unsigned b = t >> 14;            // / (16 * 1024)
    unsigned s = (t >> 10) & 15u;    // channel group (16 channels)
    unsigned q = t & 1023u;          // float4 index within plane

    float4 av = *(const float4*)(g_att + (b << 12) + (q << 2));

    const float4* xq = (const float4*)x + ((size_t)(b * 256u + s * 16u) << 10) + q;
    float4* oq = (float4*)out + ((size_t)(b * 256u + s * 16u) << 10) + q;
#pragma unroll 4
    for (int c = 0; c < 16; ++c) {
        float4 xv = __ldg(xq + ((size_t)c << 10));
        float4 o;
        o.x = xv.x * av.x;
        o.y = xv.y * av.y;
        o.z = xv.z * av.z;
        o.w = xv.w * av.w;
        oq[(size_t)c << 10] = o;
    }
}

// ---------------------------------------------------------------------------
extern "C" void kernel_launch(void* const* d_in, const int* in_sizes, int n_in,
                              void* d_out, int out_size) {
    const float* x  = (const float*)d_in[0];
    const float* w1 = (const float*)d_in[1];
    const float* g1 = (const float*)d_in[2];
    const float* b1 = (const float*)d_in[3];
    const float* m1 = (const float*)d_in[4];
    const float* v1 = (const float*)d_in[5];
    const float* w2 = (const float*)d_in[6];
    const float* g2 = (const float*)d_in[7];
    const float* b2 = (const float*)d_in[8];
    const float* m2 = (const float*)d_in[9];
    const float* v2 = (const float*)d_in[10];
    const float* w3 = (const float*)d_in[11];
    const float* g3 = (const float*)d_in[12];
    const float* b3 = (const float*)d_in[13];
    const float* m3 = (const float*)d_in[14];
    const float* v3 = (const float*)d_in[15];
    float* out = (float*)d_out;

    pool_kernel<<<(NB * PSPLIT * NQ) / 256, 256>>>(x);           // 1024 blocks
    att_kernel<<<NB * (NH / 4), 256>>>(w1, g1, b1, m1, v1,
                                       w2, g2, b2, m2, v2,
                                       w3, g3, b3, m3, v3);      // 512 blocks
    mul_kernel<<<(NB * 16 * 1024) / 256, 256>>>(x, out);         // 2048 blocks
}